// round 2
// baseline (speedup 1.0000x reference)
#include <cuda_runtime.h>
#include <cstdint>
#include <math.h>

// Problem constants
#define PP 128
#define LL 800
#define DD 200
#define HH 100
#define KK 2
#define MM 256        // P*K
#define MB 255        // M-1

// Output offsets (floats)
#define OFF_SCS 0
#define OFF_R   40960000          // M*L*D
#define OFF_ENC 40985600          // +M*H
#define OFF_V   41190400          // +M*L
#define OFF_T   41255680          // +M*(M-1)

// Copy job decomposition: job -> (m, 100-row t-segment). 256 m * 8 segs = 2048 jobs.
#define N_COPY_JOBS 2048

// Scratch
__device__ float g_c[MM * HH];
__device__ float g_o[MM * HH];
__device__ float g_alpha[MM * MB];
__device__ float g_colA[MB];

__device__ __forceinline__ float fast_tanh(float x) {
    float y;
    asm("tanh.approx.f32 %0, %1;" : "=f"(y) : "f"(x));
    return y;
}

// One copy job: masked copy of S_p rows into S_Cs for (m, t in [t0, t0+100)).
__device__ __forceinline__ void copy_job(int job, const float* __restrict__ S_p,
                                         const int* __restrict__ spans,
                                         float* __restrict__ out) {
    int m   = job >> 3;
    int t0  = (job & 7) * 100;
    int st  = spans[2 * m];
    int en  = spans[2 * m + 1];
    int p   = m >> 1;
    const float4* __restrict__ src = (const float4*)(S_p + (size_t)p * LL * DD);
    float4* __restrict__ dst = (float4*)(out + OFF_SCS + (size_t)m * LL * DD);
    const float4 z = make_float4(0.f, 0.f, 0.f, 0.f);
    // 100 t-rows * 50 float4 = 5000 float4
    #pragma unroll 4
    for (int i = threadIdx.x; i < 5000; i += 256) {
        int t = i / 50;
        int v = i - t * 50;
        t += t0;
        float4 val = (t >= st && t <= en) ? src[t * 50 + v] : z;
        dst[t * 50 + v] = val;
    }
}

// ---------------- Kernel A: r_Cs + encoded_candidates + copy slice ----------------
__global__ __launch_bounds__(256) void kA(const float* __restrict__ S_p,
                                          const int* __restrict__ spans,
                                          const int* __restrict__ passages,
                                          const float* __restrict__ Wb,
                                          const float* __restrict__ We,
                                          float* __restrict__ out,
                                          int copyBase) {
    int bid = blockIdx.x;
    int tid = threadIdx.x;
    if (bid < MM) {
        // r_Cs[m] = tanh(sb @ Wb^T + se @ We^T)
        __shared__ float sb[DD], se[DD];
        int m  = bid;
        int st = spans[2 * m];
        int en = spans[2 * m + 1];
        int p  = m >> 1;
        const float* rowb = S_p + ((size_t)p * LL + st) * DD;
        const float* rowe = S_p + ((size_t)p * LL + en) * DD;
        for (int i = tid; i < DD; i += 256) { sb[i] = rowb[i]; se[i] = rowe[i]; }
        __syncthreads();
        if (tid < HH) {
            const float* wb = Wb + tid * DD;
            const float* we = We + tid * DD;
            float acc = 0.f;
            #pragma unroll 4
            for (int d = 0; d < DD; d++) acc += sb[d] * wb[d] + se[d] * we[d];
            out[OFF_R + m * HH + tid] = tanhf(acc);
        }
    } else if (bid < 2 * MM) {
        // encoded_candidates
        int m   = bid - MM;
        int st  = spans[2 * m];
        int en  = spans[2 * m + 1];
        int len = en - st;
        int p   = m >> 1;
        for (int t = tid; t < LL; t += 256) {
            out[OFF_ENC + m * LL + t] =
                (t <= len) ? (float)passages[p * LL + st + t] : 0.0f;
        }
    } else {
        copy_job(bid - 2 * MM + copyBase, S_p, spans, out);
    }
}

// ---------------- Kernel B: c = r@Wc^T, o = r@Wo^T + copy slice ----------------
__global__ __launch_bounds__(256) void kB(const float* __restrict__ S_p,
                                          const int* __restrict__ spans,
                                          const float* __restrict__ Wc,
                                          const float* __restrict__ Wo,
                                          float* __restrict__ out,
                                          int copyBase) {
    int bid = blockIdx.x;
    int tid = threadIdx.x;
    if (bid < MM) {
        __shared__ float rs[HH];
        int m = bid;
        if (tid < HH) rs[tid] = out[OFF_R + m * HH + tid];
        __syncthreads();
        if (tid < HH) {
            const float* wc = Wc + tid * HH;
            const float* wo = Wo + tid * HH;
            float ca = 0.f, oa = 0.f;
            #pragma unroll 4
            for (int j = 0; j < HH; j++) {
                float r = rs[j];
                ca += r * wc[j];
                oa += r * wo[j];
            }
            g_c[m * HH + tid] = ca;
            g_o[m * HH + tid] = oa;
        }
    } else {
        copy_job(bid - MM + copyBase, S_p, spans, out);
    }
}

// ---------------- Kernel C: V[m,b] = sum_h tanh(c[m,h]+o[j,h])*Wv[h] + copy ----------------
__global__ __launch_bounds__(256) void kC(const float* __restrict__ S_p,
                                          const int* __restrict__ spans,
                                          const float* __restrict__ Wv,
                                          float* __restrict__ out,
                                          int copyBase) {
    int bid = blockIdx.x;
    int tid = threadIdx.x;
    if (bid < 256) {
        __shared__ float sc[16 * HH];
        __shared__ float so[17 * HH];
        __shared__ float wv[HH];
        int mt = bid >> 4, bt = bid & 15;
        int m0 = mt * 16, b0 = bt * 16;
        for (int i = tid; i < 16 * HH; i += 256) sc[i] = g_c[m0 * HH + i];
        for (int i = tid; i < 17 * HH; i += 256) {
            int j = b0 + i / HH;
            if (j < MM) so[i] = g_o[j * HH + (i % HH)];
        }
        if (tid < HH) wv[tid] = Wv[tid];
        __syncthreads();
        int ml = tid >> 4, bl = tid & 15;
        int m = m0 + ml, b = b0 + bl;
        if (b < MB) {
            int j = b + (b >= m);
            const float* cr = sc + ml * HH;
            const float* orr = so + (j - b0) * HH;
            float acc = 0.f;
            #pragma unroll 4
            for (int h = 0; h < HH; h++) {
                acc += fast_tanh(cr[h] + orr[h]) * wv[h];
            }
            out[OFF_V + m * MB + b] = acc;
        }
    } else {
        copy_job(bid - 256 + copyBase, S_p, spans, out);
    }
}

// ---------------- Kernel D: per-column E sums -> alpha, colsum(alpha) + copy ----------------
__global__ __launch_bounds__(256) void kD(const float* __restrict__ S_p,
                                          const int* __restrict__ spans,
                                          float* __restrict__ out,
                                          int copyBase) {
    int bid = blockIdx.x;
    int tid = threadIdx.x;
    if (bid < MB) {
        __shared__ float red[256];
        int b = bid;
        float v = out[OFF_V + tid * MB + b];   // tid == m (256 rows)
        float e = expf(v);
        red[tid] = e;
        __syncthreads();
        for (int s = 128; s > 0; s >>= 1) {
            if (tid < s) red[tid] += red[tid + s];
            __syncthreads();
        }
        float sumE = red[0];
        __syncthreads();
        float a = e / (sumE - e);
        g_alpha[tid * MB + b] = a;
        red[tid] = a;
        __syncthreads();
        for (int s = 128; s > 0; s >>= 1) {
            if (tid < s) red[tid] += red[tid + s];
            __syncthreads();
        }
        if (tid == 0) g_colA[b] = red[0];
    } else {
        copy_job(bid - MB + copyBase, S_p, spans, out);
    }
}

// ---------------- Kernel E: tilda_r_Cs[m,h] = sum_b s_rows[m,b]*r[j(b),h] + copy ----------------
__global__ __launch_bounds__(256) void kE(const float* __restrict__ S_p,
                                          const int* __restrict__ spans,
                                          float* __restrict__ out,
                                          int copyBase) {
    int bid = blockIdx.x;
    int tid = threadIdx.x;
    if (bid < MM) {
        __shared__ float sr[MB];
        int m = bid;
        if (tid < MB) sr[tid] = g_colA[tid] - g_alpha[m * MB + tid];
        __syncthreads();
        if (tid < HH) {
            const float* rbase = out + OFF_R;
            float acc = 0.f;
            #pragma unroll 4
            for (int b = 0; b < MB; b++) {
                int j = b + (b >= m);
                acc += sr[b] * rbase[j * HH + tid];
            }
            out[OFF_T + m * HH + tid] = acc;
        }
    } else {
        copy_job(bid - MM + copyBase, S_p, spans, out);
    }
}

extern "C" void kernel_launch(void* const* d_in, const int* in_sizes, int n_in,
                              void* d_out, int out_size) {
    const float* S_p      = (const float*)d_in[0];
    const int*   spans    = (const int*)d_in[1];
    const int*   passages = (const int*)d_in[2];
    const float* Wb       = (const float*)d_in[3];
    const float* We       = (const float*)d_in[4];
    const float* Wc       = (const float*)d_in[5];
    const float* Wo       = (const float*)d_in[6];
    const float* Wv       = (const float*)d_in[7];
    float* out = (float*)d_out;

    // Copy-job slices: 410+410+410+410+408 = 2048
    kA<<<512 + 410, 256>>>(S_p, spans, passages, Wb, We, out, 0);
    kB<<<256 + 410, 256>>>(S_p, spans, Wc, Wo, out, 410);
    kC<<<256 + 410, 256>>>(S_p, spans, Wv, out, 820);
    kD<<<255 + 410, 256>>>(S_p, spans, out, 1230);
    kE<<<256 + 408, 256>>>(S_p, spans, out, 1640);
}

// round 3
// speedup vs baseline: 1.1475x; 1.1475x over previous
#include <cuda_runtime.h>
#include <cstdint>
#include <math.h>

// Problem constants
#define PP 128
#define LL 800
#define DD 200
#define HH 100
#define MM 256        // P*K
#define MB 255        // M-1

// Output offsets (floats)
#define OFF_SCS 0
#define OFF_R   40960000          // M*L*D
#define OFF_ENC 40985600          // +M*H
#define OFF_V   41190400          // +M*L
#define OFF_T   41255680          // +M*(M-1)

#define SEG_ROWS 100              // t-rows per copy job
#define NJOBS 2048                // 256 m * 8 segments

// Scratch
__device__ float g_cT[HH * MM];   // transposed: [h][m] for coalesced reads in k2
__device__ float g_o[MM * HH];
__device__ float g_alpha[MM * MB];
__device__ float g_colA[MB];

__device__ __forceinline__ float fast_tanh(float x) {
    float y;
    asm("tanh.approx.f32 %0, %1;" : "=f"(y) : "f"(x));
    return y;
}

// Masked copy of S_p rows into S_Cs for (m, t in [t0, t0+100)).
// Row-level warp-uniform branching: zero rows are pure STG streams,
// in-span rows are LDG.128 -> STG.128. 2 rows per warp-iteration for MLP.
__device__ __forceinline__ void copy_job(int job, const float* __restrict__ S_p,
                                         const int* __restrict__ spans,
                                         float* __restrict__ out) {
    int m  = job >> 3;
    int t0 = (job & 7) * SEG_ROWS;
    int st = spans[2 * m];
    int en = spans[2 * m + 1];
    int p  = m >> 1;
    const float4* __restrict__ src = (const float4*)(S_p + (size_t)p * LL * DD);
    float4* __restrict__ dst = (float4*)(out + (size_t)m * LL * DD);
    int warp = threadIdx.x >> 5;
    int lane = threadIdx.x & 31;
    bool hi = (lane < 18);
    const float4 z = make_float4(0.f, 0.f, 0.f, 0.f);
    // 50 float4 per row: lane covers idx {lane, lane+32 (pred lane<18)}
    for (int t = t0 + 2 * warp; t < t0 + SEG_ROWS; t += 16) {
        int t1 = t + 1;
        bool in0 = (t  >= st) && (t  <= en);
        bool in1 = (t1 >= st) && (t1 <= en);
        float4 a0 = z, b0 = z, a1 = z, b1 = z;
        if (in0) {
            a0 = src[t * 50 + lane];
            if (hi) b0 = src[t * 50 + lane + 32];
        }
        if (in1) {
            a1 = src[t1 * 50 + lane];
            if (hi) b1 = src[t1 * 50 + lane + 32];
        }
        dst[t * 50 + lane] = a0;
        if (hi) dst[t * 50 + lane + 32] = b0;
        dst[t1 * 50 + lane] = a1;
        if (hi) dst[t1 * 50 + lane + 32] = b1;
    }
}

// ---------------- k1: r_Cs, c, o (fused), encoded_candidates + copy ----------------
__global__ __launch_bounds__(256) void k1(const float* __restrict__ S_p,
                                          const int* __restrict__ spans,
                                          const int* __restrict__ passages,
                                          const float* __restrict__ Wb,
                                          const float* __restrict__ We,
                                          const float* __restrict__ Wc,
                                          const float* __restrict__ Wo,
                                          float* __restrict__ out,
                                          int copyBase) {
    int bid = blockIdx.x;
    int tid = threadIdx.x;
    if (bid < MM) {
        __shared__ float sb[DD], se[DD], rs[HH];
        int m  = bid;
        int st = spans[2 * m];
        int en = spans[2 * m + 1];
        int p  = m >> 1;
        const float* rowb = S_p + ((size_t)p * LL + st) * DD;
        const float* rowe = S_p + ((size_t)p * LL + en) * DD;
        for (int i = tid; i < DD; i += 256) { sb[i] = rowb[i]; se[i] = rowe[i]; }
        __syncthreads();
        if (tid < HH) {
            const float* wb = Wb + tid * DD;
            const float* we = We + tid * DD;
            float acc = 0.f;
            #pragma unroll 4
            for (int d = 0; d < DD; d++) acc += sb[d] * wb[d] + se[d] * we[d];
            float r = tanhf(acc);
            out[OFF_R + m * HH + tid] = r;
            rs[tid] = r;
        }
        __syncthreads();
        if (tid < HH) {
            const float* wc = Wc + tid * HH;
            const float* wo = Wo + tid * HH;
            float ca = 0.f, oa = 0.f;
            #pragma unroll 4
            for (int j = 0; j < HH; j++) {
                float r = rs[j];
                ca += r * wc[j];
                oa += r * wo[j];
            }
            g_cT[tid * MM + m] = ca;      // transposed store
            g_o[m * HH + tid] = oa;
        }
    } else if (bid < 2 * MM) {
        int m   = bid - MM;
        int st  = spans[2 * m];
        int en  = spans[2 * m + 1];
        int len = en - st;
        int p   = m >> 1;
        for (int t = tid; t < LL; t += 256) {
            out[OFF_ENC + m * LL + t] =
                (t <= len) ? (float)passages[p * LL + st + t] : 0.0f;
        }
    } else {
        copy_job(copyBase + bid - 2 * MM, S_p, spans, out);
    }
}

// ---------------- k2: V column + sumE + alpha + colA (fused) + copy ----------------
// One block per column b. j = b + (b >= m) means only o[b] and o[b+1] are needed.
__global__ __launch_bounds__(256) void k2(const float* __restrict__ S_p,
                                          const int* __restrict__ spans,
                                          const float* __restrict__ Wv,
                                          float* __restrict__ out,
                                          int copyBase) {
    int bid = blockIdx.x;
    int tid = threadIdx.x;
    if (bid < MB) {
        __shared__ float so0[HH], so1[HH], wv[HH];
        __shared__ float red[256];
        int b = bid;
        if (tid < HH) {
            so0[tid] = g_o[b * HH + tid];
            so1[tid] = g_o[(b + 1) * HH + tid];
            wv[tid]  = Wv[tid];
        }
        __syncthreads();
        int m = tid;                       // 256 threads == 256 rows
        const float* oo = (b >= m) ? so1 : so0;
        float acc = 0.f;
        #pragma unroll 4
        for (int h = 0; h < HH; h++)
            acc += fast_tanh(g_cT[h * MM + m] + oo[h]) * wv[h];   // coalesced LDG
        out[OFF_V + m * MB + b] = acc;
        float e = __expf(acc);
        red[tid] = e;
        __syncthreads();
        for (int s = 128; s > 0; s >>= 1) {
            if (tid < s) red[tid] += red[tid + s];
            __syncthreads();
        }
        float sumE = red[0];
        __syncthreads();
        float a = e / (sumE - e);
        g_alpha[m * MB + b] = a;
        red[tid] = a;
        __syncthreads();
        for (int s = 128; s > 0; s >>= 1) {
            if (tid < s) red[tid] += red[tid + s];
            __syncthreads();
        }
        if (tid == 0) g_colA[b] = red[0];
    } else {
        copy_job(copyBase + bid - MB, S_p, spans, out);
    }
}

// ---------------- k3: tilda_r_Cs + copy ----------------
__global__ __launch_bounds__(256) void k3(const float* __restrict__ S_p,
                                          const int* __restrict__ spans,
                                          float* __restrict__ out,
                                          int copyBase) {
    int bid = blockIdx.x;
    int tid = threadIdx.x;
    if (bid < MM) {
        __shared__ float sr[MB];
        int m = bid;
        if (tid < MB) sr[tid] = g_colA[tid] - g_alpha[m * MB + tid];
        __syncthreads();
        if (tid < HH) {
            const float* rbase = out + OFF_R;
            float acc = 0.f;
            #pragma unroll 4
            for (int b = 0; b < MB; b++) {
                int j = b + (b >= m);
                acc += sr[b] * rbase[j * HH + tid];
            }
            out[OFF_T + m * HH + tid] = acc;
        }
    } else {
        copy_job(copyBase + bid - MM, S_p, spans, out);
    }
}

extern "C" void kernel_launch(void* const* d_in, const int* in_sizes, int n_in,
                              void* d_out, int out_size) {
    const float* S_p      = (const float*)d_in[0];
    const int*   spans    = (const int*)d_in[1];
    const int*   passages = (const int*)d_in[2];
    const float* Wb       = (const float*)d_in[3];
    const float* We       = (const float*)d_in[4];
    const float* Wc       = (const float*)d_in[5];
    const float* Wo       = (const float*)d_in[6];
    const float* Wv       = (const float*)d_in[7];
    float* out = (float*)d_out;

    // Copy-job split: 683 + 683 + 682 = 2048
    k1<<<512 + 683, 256>>>(S_p, spans, passages, Wb, We, Wc, Wo, out, 0);
    k2<<<255 + 683, 256>>>(S_p, spans, Wv, out, 683);
    k3<<<256 + 682, 256>>>(S_p, spans, out, 1366);
}

// round 4
// speedup vs baseline: 1.2871x; 1.1216x over previous
#include <cuda_runtime.h>
#include <cstdint>
#include <math.h>

// Problem constants
#define PP 128
#define LL 800
#define DD 200
#define HH 100
#define MM 256        // P*K
#define MB 255        // M-1

// Output offsets (floats)
#define OFF_SCS 0
#define OFF_R   40960000          // M*L*D
#define OFF_ENC 40985600          // +M*H
#define OFF_V   41190400          // +M*L
#define OFF_T   41255680          // +M*(M-1)

#define SEG_ROWS 50               // t-rows per copy job
#define NJOBS 4096                // 256 m * 16 segments

// Scratch
__device__ float g_cT[HH * MM];   // transposed: [h][m] for coalesced reads in k2
__device__ float g_o[MM * HH];
__device__ float g_alpha[MM * MB];
__device__ float g_colA[MB];

__device__ __forceinline__ float fast_tanh(float x) {
    float y;
    asm("tanh.approx.f32 %0, %1;" : "=f"(y) : "f"(x));
    return y;
}

__device__ __forceinline__ float warp_sum(float v) {
    #pragma unroll
    for (int o = 16; o; o >>= 1) v += __shfl_down_sync(0xffffffffu, v, o);
    return v;
}

// Masked copy of S_p rows into S_Cs for (m, t in [t0, t0+50)).
// Row-level warp-uniform branching: zero rows are pure STG streams,
// in-span rows are LDG.128 -> STG.128. 2 rows per warp-iteration for MLP.
__device__ __forceinline__ void copy_job(int job, const float* __restrict__ S_p,
                                         const int* __restrict__ spans,
                                         float* __restrict__ out) {
    int m  = job >> 4;
    int t0 = (job & 15) * SEG_ROWS;
    int st = spans[2 * m];
    int en = spans[2 * m + 1];
    int p  = m >> 1;
    const float4* __restrict__ src = (const float4*)(S_p + (size_t)p * LL * DD);
    float4* __restrict__ dst = (float4*)(out + (size_t)m * LL * DD);
    int warp = threadIdx.x >> 5;
    int lane = threadIdx.x & 31;
    bool hi = (lane < 18);
    const float4 z = make_float4(0.f, 0.f, 0.f, 0.f);
    // 50 float4 per row: lane covers idx {lane, lane+32 (pred lane<18)}
    for (int t = t0 + 2 * warp; t < t0 + SEG_ROWS; t += 16) {
        int t1 = t + 1;
        bool in0 = (t  >= st) && (t  <= en);
        bool in1 = (t1 >= st) && (t1 <= en);
        float4 a0 = z, b0 = z, a1 = z, b1 = z;
        if (in0) {
            a0 = src[t * 50 + lane];
            if (hi) b0 = src[t * 50 + lane + 32];
        }
        if (in1) {
            a1 = src[t1 * 50 + lane];
            if (hi) b1 = src[t1 * 50 + lane + 32];
        }
        dst[t * 50 + lane] = a0;
        if (hi) dst[t * 50 + lane + 32] = b0;
        dst[t1 * 50 + lane] = a1;
        if (hi) dst[t1 * 50 + lane + 32] = b1;
    }
}

// ---------------- k1: per-m r_Cs, c, o, encoded_candidates (warp-GEMV) + copy ----------------
__global__ __launch_bounds__(256) void k1(const float* __restrict__ S_p,
                                          const int* __restrict__ spans,
                                          const int* __restrict__ passages,
                                          const float* __restrict__ Wb,
                                          const float* __restrict__ We,
                                          const float* __restrict__ Wc,
                                          const float* __restrict__ Wo,
                                          float* __restrict__ out,
                                          int copyBase) {
    int bid = blockIdx.x;
    int tid = threadIdx.x;
    if (bid < MM) {
        __shared__ float sb[DD], se[DD], rs[HH];
        int m  = bid;
        int st = spans[2 * m];
        int en = spans[2 * m + 1];
        int p  = m >> 1;
        const float* rowb = S_p + ((size_t)p * LL + st) * DD;
        const float* rowe = S_p + ((size_t)p * LL + en) * DD;
        for (int i = tid; i < DD; i += 256) { sb[i] = rowb[i]; se[i] = rowe[i]; }
        __syncthreads();
        int warp = tid >> 5, lane = tid & 31;
        // r[h] = tanh(sb.Wb[h] + se.We[h])  — warp per h, coalesced weight reads
        for (int h = warp; h < HH; h += 8) {
            const float* wb = Wb + h * DD;
            const float* we = We + h * DD;
            float a = 0.f;
            #pragma unroll
            for (int d = lane; d < DD; d += 32) a += sb[d] * wb[d] + se[d] * we[d];
            a = warp_sum(a);
            if (lane == 0) {
                float r = tanhf(a);
                rs[h] = r;
                out[OFF_R + m * HH + h] = r;
            }
        }
        __syncthreads();
        // c[h] = r.Wc[h], o[h] = r.Wo[h]
        for (int h = warp; h < HH; h += 8) {
            const float* wc = Wc + h * HH;
            const float* wo = Wo + h * HH;
            float ca = 0.f, oa = 0.f;
            #pragma unroll
            for (int j = lane; j < HH; j += 32) {
                float r = rs[j];
                ca += r * wc[j];
                oa += r * wo[j];
            }
            ca = warp_sum(ca);
            oa = warp_sum(oa);
            if (lane == 0) {
                g_cT[h * MM + m] = ca;
                g_o[m * HH + h] = oa;
            }
        }
        // encoded_candidates (no sync needed; independent)
        int len = en - st;
        for (int t = tid; t < LL; t += 256) {
            out[OFF_ENC + m * LL + t] =
                (t <= len) ? (float)passages[p * LL + st + t] : 0.0f;
        }
    } else {
        copy_job(copyBase + bid - MM, S_p, spans, out);
    }
}

// ---------------- k2: V column + sumE + alpha + colA (fused) + copy ----------------
// One block per column b. j = b + (b >= m) means only o[b] and o[b+1] are needed.
__global__ __launch_bounds__(256) void k2(const float* __restrict__ S_p,
                                          const int* __restrict__ spans,
                                          const float* __restrict__ Wv,
                                          float* __restrict__ out,
                                          int copyBase) {
    int bid = blockIdx.x;
    int tid = threadIdx.x;
    if (bid < MB) {
        __shared__ float so0[HH], so1[HH], wv[HH];
        __shared__ float red[256];
        int b = bid;
        if (tid < HH) {
            so0[tid] = g_o[b * HH + tid];
            so1[tid] = g_o[(b + 1) * HH + tid];
            wv[tid]  = Wv[tid];
        }
        __syncthreads();
        int m = tid;                       // 256 threads == 256 rows
        const float* oo = (b >= m) ? so1 : so0;
        float acc = 0.f;
        #pragma unroll 4
        for (int h = 0; h < HH; h++)
            acc += fast_tanh(g_cT[h * MM + m] + oo[h]) * wv[h];   // coalesced LDG
        out[OFF_V + m * MB + b] = acc;
        float e = __expf(acc);
        red[tid] = e;
        __syncthreads();
        for (int s = 128; s > 0; s >>= 1) {
            if (tid < s) red[tid] += red[tid + s];
            __syncthreads();
        }
        float sumE = red[0];
        __syncthreads();
        float a = e / (sumE - e);
        g_alpha[m * MB + b] = a;
        red[tid] = a;
        __syncthreads();
        for (int s = 128; s > 0; s >>= 1) {
            if (tid < s) red[tid] += red[tid + s];
            __syncthreads();
        }
        if (tid == 0) g_colA[b] = red[0];
    } else {
        copy_job(copyBase + bid - MB, S_p, spans, out);
    }
}

// ---------------- k3: tilda_r_Cs + copy ----------------
__global__ __launch_bounds__(256) void k3(const float* __restrict__ S_p,
                                          const int* __restrict__ spans,
                                          float* __restrict__ out,
                                          int copyBase) {
    int bid = blockIdx.x;
    int tid = threadIdx.x;
    if (bid < MM) {
        __shared__ float sr[MB];
        int m = bid;
        if (tid < MB) sr[tid] = g_colA[tid] - g_alpha[m * MB + tid];
        __syncthreads();
        if (tid < HH) {
            const float* rbase = out + OFF_R;
            float acc = 0.f;
            #pragma unroll 4
            for (int b = 0; b < MB; b++) {
                int j = b + (b >= m);
                acc += sr[b] * rbase[j * HH + tid];   // j uniform -> coalesced
            }
            out[OFF_T + m * HH + tid] = acc;
        }
    } else {
        copy_job(copyBase + bid - MM, S_p, spans, out);
    }
}

extern "C" void kernel_launch(void* const* d_in, const int* in_sizes, int n_in,
                              void* d_out, int out_size) {
    const float* S_p      = (const float*)d_in[0];
    const int*   spans    = (const int*)d_in[1];
    const int*   passages = (const int*)d_in[2];
    const float* Wb       = (const float*)d_in[3];
    const float* We       = (const float*)d_in[4];
    const float* Wc       = (const float*)d_in[5];
    const float* Wo       = (const float*)d_in[6];
    const float* Wv       = (const float*)d_in[7];
    float* out = (float*)d_out;

    // Copy-job split: 1300 + 1398 + 1398 = 4096
    k1<<<256 + 1300, 256>>>(S_p, spans, passages, Wb, We, Wc, Wo, out, 0);
    k2<<<255 + 1398, 256>>>(S_p, spans, Wv, out, 1300);
    k3<<<256 + 1398, 256>>>(S_p, spans, out, 2698);
}

// round 5
// speedup vs baseline: 1.6474x; 1.2799x over previous
#include <cuda_runtime.h>
#include <cstdint>
#include <math.h>

// Problem constants
#define PP 128
#define LL 800
#define DD 200
#define HH 100
#define MM 256        // P*K
#define MB 255        // M-1

// Output offsets (floats)
#define OFF_SCS 0
#define OFF_R   40960000          // M*L*D
#define OFF_ENC 40985600          // +M*H
#define OFF_V   41190400          // +M*L
#define OFF_T   41255680          // +M*(M-1)

#define SEG_ROWS 50               // t-rows per copy job
#define NJOBS 4096                // 256 m * 16 segments

// Scratch
__device__ float g_cT[HH * MM];   // transposed: [h][m] for coalesced reads in k2
__device__ float g_o[MM * HH];
__device__ float g_alpha[MM * MB];
__device__ float g_colA[MB];

__device__ __forceinline__ float fast_tanh(float x) {
    float y;
    asm("tanh.approx.f32 %0, %1;" : "=f"(y) : "f"(x));
    return y;
}

__device__ __forceinline__ float warp_sum(float v) {
    #pragma unroll
    for (int o = 16; o; o >>= 1) v += __shfl_down_sync(0xffffffffu, v, o);
    return v;
}

// Masked copy of S_p rows into S_Cs for (m, t in [t0, t0+SEG_ROWS)).
// The span mask is contiguous in t, so the job splits into three FLAT
// contiguous float4 ranges: zero-prefix, copy-middle, zero-suffix.
// Pure streaming loops, no per-element predication, __stcs to bypass L2 reuse.
__device__ __forceinline__ void copy_job(int job, const float* __restrict__ S_p,
                                         const int* __restrict__ spans,
                                         float* __restrict__ out) {
    int m  = job >> 4;
    int t0 = (job & 15) * SEG_ROWS;
    int t1 = t0 + SEG_ROWS;
    int st = spans[2 * m];
    int en = spans[2 * m + 1];
    int p  = m >> 1;
    int c0 = max(st, t0);
    int c1 = min(en + 1, t1);
    if (c0 >= c1) { c0 = t0; c1 = t0; }   // no overlap: zero everything

    const float4* __restrict__ src = (const float4*)(S_p + (size_t)p * LL * DD);
    float4* __restrict__ dst = (float4*)(out + (size_t)m * LL * DD);
    const float4 z = make_float4(0.f, 0.f, 0.f, 0.f);
    int tid = threadIdx.x;

    // zero-prefix: rows [t0, c0)  -> flat float4 [t0*50, c0*50)
    {
        int lo = t0 * 50, hi = c0 * 50;
        #pragma unroll 4
        for (int i = lo + tid; i < hi; i += 256) __stcs(&dst[i], z);
    }
    // copy-middle: rows [c0, c1) -> flat [c0*50, c1*50), same flat offset in src
    {
        int lo = c0 * 50, hi = c1 * 50;
        #pragma unroll 4
        for (int i = lo + tid; i < hi; i += 256) __stcs(&dst[i], src[i]);
    }
    // zero-suffix: rows [c1, t1)
    {
        int lo = c1 * 50, hi = t1 * 50;
        #pragma unroll 4
        for (int i = lo + tid; i < hi; i += 256) __stcs(&dst[i], z);
    }
}

// ---------------- k1: per-m r_Cs, c, o, encoded_candidates (warp-GEMV) + copy ----------------
__global__ __launch_bounds__(256) void k1(const float* __restrict__ S_p,
                                          const int* __restrict__ spans,
                                          const int* __restrict__ passages,
                                          const float* __restrict__ Wb,
                                          const float* __restrict__ We,
                                          const float* __restrict__ Wc,
                                          const float* __restrict__ Wo,
                                          float* __restrict__ out,
                                          int copyBase) {
    int bid = blockIdx.x;
    int tid = threadIdx.x;
    if (bid < MM) {
        __shared__ float sb[DD], se[DD], rs[HH];
        int m  = bid;
        int st = spans[2 * m];
        int en = spans[2 * m + 1];
        int p  = m >> 1;
        const float* rowb = S_p + ((size_t)p * LL + st) * DD;
        const float* rowe = S_p + ((size_t)p * LL + en) * DD;
        for (int i = tid; i < DD; i += 256) { sb[i] = rowb[i]; se[i] = rowe[i]; }
        __syncthreads();
        int warp = tid >> 5, lane = tid & 31;
        // r[h] = tanh(sb.Wb[h] + se.We[h])  — warp per h, coalesced weight reads
        for (int h = warp; h < HH; h += 8) {
            const float* wb = Wb + h * DD;
            const float* we = We + h * DD;
            float a = 0.f;
            #pragma unroll
            for (int d = lane; d < DD; d += 32) a += sb[d] * wb[d] + se[d] * we[d];
            a = warp_sum(a);
            if (lane == 0) {
                float r = tanhf(a);
                rs[h] = r;
                out[OFF_R + m * HH + h] = r;
            }
        }
        __syncthreads();
        // c[h] = r.Wc[h], o[h] = r.Wo[h]
        for (int h = warp; h < HH; h += 8) {
            const float* wc = Wc + h * HH;
            const float* wo = Wo + h * HH;
            float ca = 0.f, oa = 0.f;
            #pragma unroll
            for (int j = lane; j < HH; j += 32) {
                float r = rs[j];
                ca += r * wc[j];
                oa += r * wo[j];
            }
            ca = warp_sum(ca);
            oa = warp_sum(oa);
            if (lane == 0) {
                g_cT[h * MM + m] = ca;
                g_o[m * HH + h] = oa;
            }
        }
        // encoded_candidates (independent)
        int len = en - st;
        for (int t = tid; t < LL; t += 256) {
            out[OFF_ENC + m * LL + t] =
                (t <= len) ? (float)passages[p * LL + st + t] : 0.0f;
        }
    } else {
        copy_job(copyBase + bid - MM, S_p, spans, out);
    }
}

// ---------------- k2: V column + sumE + alpha + colA (fused) + copy ----------------
// One block per column b. j = b + (b >= m) means only o[b] and o[b+1] are needed.
__global__ __launch_bounds__(256) void k2(const float* __restrict__ S_p,
                                          const int* __restrict__ spans,
                                          const float* __restrict__ Wv,
                                          float* __restrict__ out,
                                          int copyBase) {
    int bid = blockIdx.x;
    int tid = threadIdx.x;
    if (bid < MB) {
        __shared__ float so0[HH], so1[HH], wv[HH];
        __shared__ float red[256];
        int b = bid;
        if (tid < HH) {
            so0[tid] = g_o[b * HH + tid];
            so1[tid] = g_o[(b + 1) * HH + tid];
            wv[tid]  = Wv[tid];
        }
        __syncthreads();
        int m = tid;                       // 256 threads == 256 rows
        const float* oo = (b >= m) ? so1 : so0;
        float acc = 0.f;
        #pragma unroll 8
        for (int h = 0; h < HH; h++)
            acc += fast_tanh(g_cT[h * MM + m] + oo[h]) * wv[h];   // coalesced LDG
        out[OFF_V + m * MB + b] = acc;
        float e = __expf(acc);
        red[tid] = e;
        __syncthreads();
        for (int s = 128; s > 0; s >>= 1) {
            if (tid < s) red[tid] += red[tid + s];
            __syncthreads();
        }
        float sumE = red[0];
        __syncthreads();
        float a = e / (sumE - e);
        g_alpha[m * MB + b] = a;
        red[tid] = a;
        __syncthreads();
        for (int s = 128; s > 0; s >>= 1) {
            if (tid < s) red[tid] += red[tid + s];
            __syncthreads();
        }
        if (tid == 0) g_colA[b] = red[0];
    } else {
        copy_job(copyBase + bid - MB, S_p, spans, out);
    }
}

// ---------------- k3: tilda_r_Cs (2-way b-split) + copy ----------------
__global__ __launch_bounds__(256) void k3(const float* __restrict__ S_p,
                                          const int* __restrict__ spans,
                                          float* __restrict__ out,
                                          int copyBase) {
    int bid = blockIdx.x;
    int tid = threadIdx.x;
    if (bid < MM) {
        __shared__ float sr[MB];
        __shared__ float partial[HH];
        int m = bid;
        if (tid < MB) sr[tid] = g_colA[tid] - g_alpha[m * MB + tid];
        __syncthreads();
        int half = tid >> 7;          // 0 or 1
        int h    = tid & 127;
        float acc = 0.f;
        if (h < HH) {
            const float* rbase = out + OFF_R;
            int b0 = half ? 128 : 0;
            int b1 = half ? MB : 128;
            #pragma unroll 4
            for (int b = b0; b < b1; b++) {
                int j = b + (b >= m);
                acc += sr[b] * rbase[j * HH + h];   // j uniform -> coalesced
            }
        }
        if (half == 0 && h < HH) partial[h] = acc;
        __syncthreads();
        if (half == 1 && h < HH) out[OFF_T + m * HH + h] = acc + partial[h];
    } else {
        copy_job(copyBase + bid - MM, S_p, spans, out);
    }
}

extern "C" void kernel_launch(void* const* d_in, const int* in_sizes, int n_in,
                              void* d_out, int out_size) {
    const float* S_p      = (const float*)d_in[0];
    const int*   spans    = (const int*)d_in[1];
    const int*   passages = (const int*)d_in[2];
    const float* Wb       = (const float*)d_in[3];
    const float* We       = (const float*)d_in[4];
    const float* Wc       = (const float*)d_in[5];
    const float* Wo       = (const float*)d_in[6];
    const float* Wv       = (const float*)d_in[7];
    float* out = (float*)d_out;

    // Copy-job split: 1200 + 1448 + 1448 = 4096
    k1<<<256 + 1200, 256>>>(S_p, spans, passages, Wb, We, Wc, Wo, out, 0);
    k2<<<255 + 1448, 256>>>(S_p, spans, Wv, out, 1200);
    k3<<<256 + 1448, 256>>>(S_p, spans, out, 2648);
}